// round 15
// baseline (speedup 1.0000x reference)
#include <cuda_runtime.h>
#include <math.h>

#define N_NODES 6144
#define F_IN    256
#define F_HID   64
#define F_OUT   32
#define NHEADS  4

// ---------------- scratch (device globals; no allocation allowed) ----------
__device__ float  g_H1[N_NODES * F_HID * NHEADS];   // layer-1 per-head features, [N][4*64]
__device__ float  g_Wp[F_IN * F_HID * NHEADS];      // repacked W_heads -> [256][256]
__device__ float  g_s1[NHEADS * N_NODES];
__device__ float  g_s2[NHEADS * N_NODES];
__device__ float  g_s2max[NHEADS];
__device__ float4 g_RowP[NHEADS * N_NODES];         // {A=exp(s1-m), B=exp(0.2 s1-m), s1, 0}
__device__ float4 g_ColP[NHEADS * N_NODES];         // {s2, C=exp(s2), D=exp(0.2 s2), 0}
__device__ float  g_OutAcc1[N_NODES * F_HID * NHEADS];
__device__ float  g_Den1[NHEADS * N_NODES];
__device__ float  g_X2[N_NODES * F_HID];
__device__ float  g_H2[N_NODES * F_OUT];
__device__ float  g_OutAcc2[N_NODES * F_OUT];
__device__ float  g_Den2[N_NODES];

// ---------------- small kernels --------------------------------------------
__global__ void zero_kernel(float* __restrict__ p, int n) {
    int i = blockIdx.x * 256 + threadIdx.x;
    if (i < n) p[i] = 0.f;
}

// W_heads [H][F_IN][F_HID] -> Wp [F_IN][H*F_HID] (col = h*64+f)
__global__ void repack_kernel(const float* __restrict__ W, float* __restrict__ Wp) {
    int idx = blockIdx.x * 256 + threadIdx.x;          // < 256*256
    int k = idx >> 8;
    int c = idx & 255;
    int h = c >> 6;
    int f = c & 63;
    Wp[idx] = W[h * (F_IN * F_HID) + k * F_HID + f];
}

// C[M][Ncol] = A[M][K] @ B[K][Ncol].  M % 64 == 0, K % 16 == 0. 256 threads.
__global__ void gemm_kernel(const float* __restrict__ A, const float* __restrict__ B,
                            float* __restrict__ C, int M, int Ncol, int K) {
    __shared__ float As[16][65];
    __shared__ float Bs[16][64];
    int tid = threadIdx.x;
    int tx = tid & 15, ty = tid >> 4;
    int rowBase = blockIdx.y * 64, colBase = blockIdx.x * 64;
    float acc[4][4] = {};
    for (int k0 = 0; k0 < K; k0 += 16) {
        for (int l = tid; l < 64 * 16; l += 256) {
            int r = l >> 4, kk = l & 15;
            As[kk][r] = A[(size_t)(rowBase + r) * K + k0 + kk];
        }
        for (int l = tid; l < 16 * 64; l += 256) {
            int kk = l >> 6, n = l & 63;
            int col = colBase + n;
            Bs[kk][n] = (col < Ncol) ? B[(size_t)(k0 + kk) * Ncol + col] : 0.f;
        }
        __syncthreads();
#pragma unroll
        for (int kk = 0; kk < 16; kk++) {
            float a[4], b[4];
#pragma unroll
            for (int i = 0; i < 4; i++) a[i] = As[kk][ty * 4 + i];
#pragma unroll
            for (int j = 0; j < 4; j++) b[j] = Bs[kk][tx * 4 + j];
#pragma unroll
            for (int i = 0; i < 4; i++)
#pragma unroll
                for (int j = 0; j < 4; j++) acc[i][j] = fmaf(a[i], b[j], acc[i][j]);
        }
        __syncthreads();
    }
#pragma unroll
    for (int i = 0; i < 4; i++) {
        int row = rowBase + ty * 4 + i;
#pragma unroll
        for (int j = 0; j < 4; j++) {
            int col = colBase + tx * 4 + j;
            if (col < Ncol) C[(size_t)row * Ncol + col] = acc[i][j];
        }
    }
}

// s1[h*N+i] = H[i, h*F:(h+1)*F] . a[h][0:F];  s2 with a[h][F:2F]. One warp per (h,i).
__global__ void score_kernel(const float* __restrict__ H, const float* __restrict__ a,
                             float* __restrict__ s1o, float* __restrict__ s2o,
                             int N, int F, int heads) {
    int gt = blockIdx.x * blockDim.x + threadIdx.x;
    int w = gt >> 5, lane = gt & 31;
    if (w >= N * heads) return;
    int h = w / N, i = w - h * N;
    const float* hr = H + (size_t)i * F * heads + h * F;
    const float* a1 = a + h * 2 * F;
    const float* a2 = a1 + F;
    float p1 = 0.f, p2 = 0.f;
    for (int f = lane; f < F; f += 32) {
        float hv = hr[f];
        p1 = fmaf(hv, a1[f], p1);
        p2 = fmaf(hv, a2[f], p2);
    }
#pragma unroll
    for (int o = 16; o; o >>= 1) {
        p1 += __shfl_down_sync(0xffffffffu, p1, o);
        p2 += __shfl_down_sync(0xffffffffu, p2, o);
    }
    if (lane == 0) { s1o[w] = p1; s2o[w] = p2; }
}

__global__ void s2max_kernel(const float* __restrict__ s2, float* __restrict__ out, int N) {
    __shared__ float sm[256];
    const float* p = s2 + (size_t)blockIdx.x * N;
    float m = -1e30f;
    for (int i = threadIdx.x; i < N; i += 256) m = fmaxf(m, p[i]);
    sm[threadIdx.x] = m;
    __syncthreads();
    for (int s = 128; s; s >>= 1) {
        if (threadIdx.x < s) sm[threadIdx.x] = fmaxf(sm[threadIdx.x], sm[threadIdx.x + s]);
        __syncthreads();
    }
    if (threadIdx.x == 0) out[blockIdx.x] = sm[0];
}

__global__ void param_kernel(const float* __restrict__ s1, const float* __restrict__ s2,
                             const float* __restrict__ s2max,
                             float4* __restrict__ RowP, float4* __restrict__ ColP,
                             int N, int heads) {
    int idx = blockIdx.x * 256 + threadIdx.x;
    if (idx >= N * heads) return;
    int h = idx / N;
    float sv1 = s1[idx], sv2 = s2[idx];
    float t = sv1 + s2max[h];
    float m = (t > 0.f) ? t : 0.2f * t;                 // upper bound of row max (shift-safe)
    RowP[idx] = make_float4(expf(sv1 - m), expf(0.2f * sv1 - m), sv1, 0.f);
    ColP[idx] = make_float4(sv2, expf(sv2), expf(0.2f * sv2), 0.f);
}

// ---------------- heavy masked-attention aggregate --------------------------
// OutAcc[i][f] += sum_j w(h(f),i,j) * H[j][f];  Den[h][i] += sum_j w(h,i,j)
// w(h,i,j) = adj[i][j] ? ((s1+s2>=0) ? A_i*C_j : B_i*D_j) : 0   (all per head h)
template <int BM, int BJ, int HEADS, int F, int RPT, int FPT>
__global__ void __launch_bounds__(256, 2)
heavy_kernel(const int* __restrict__ adj, const float* __restrict__ H,
             const float4* __restrict__ RowP, const float4* __restrict__ ColP,
             float* __restrict__ OutAcc, float* __restrict__ Den,
             int N, int jPerBlock) {
    constexpr int FPH    = F / HEADS;
    constexpr int FG     = F / FPT;
    constexpr int PAIRS  = HEADS * BM;
    constexpr int NSLICE = 256 / PAIRS;
    constexpr int JS     = BJ / NSLICE;
    static_assert((BM / RPT) * FG == 256, "thread map");
    static_assert(256 % PAIRS == 0 && BJ % NSLICE == 0, "build map");

    extern __shared__ float smem[];
    float*  Hs   = smem;                                 // [BJ][F]
    float*  Ws   = Hs + BJ * F;                          // [BJ][HEADS*BM]
    int*    adjS = (int*)(Ws + BJ * PAIRS);              // [BM][BJ+1] (pad kills conflicts)
    float4* colS = (float4*)(adjS + BM * (BJ + 1));      // [BJ][HEADS]

    int tid = threadIdx.x;
    int rowBase = blockIdx.x * BM;
    int jBase0  = blockIdx.y * jPerBlock;

    // GEMM-phase mapping
    int rg = tid / FG, fg = tid % FG;
    int r0 = rg * RPT, f0 = fg * FPT;
    int headF = f0 / FPH;

    // build-phase mapping
    int p = tid % PAIRS;
    int slice = tid / PAIRS;
    int h_b = p / BM, r_b = p % BM;
    float4 rp = RowP[(size_t)h_b * N + rowBase + r_b];
    float denom_acc = 0.f;

    float acc[RPT][FPT];
#pragma unroll
    for (int r = 0; r < RPT; r++)
#pragma unroll
        for (int f = 0; f < FPT; f++) acc[r][f] = 0.f;

    for (int jc = 0; jc < jPerBlock; jc += BJ) {
        int jBase = jBase0 + jc;
        // stage adj tile (coalesced)
        for (int l = tid; l < BM * BJ; l += 256) {
            int r = l / BJ, j = l % BJ;
            adjS[r * (BJ + 1) + j] = adj[(size_t)(rowBase + r) * N + jBase + j];
        }
        // stage H chunk (rows jBase..jBase+BJ are contiguous)
        for (int l = tid; l < BJ * F / 4; l += 256)
            ((float4*)Hs)[l] = ((const float4*)H)[(size_t)jBase * (F / 4) + l];
        // stage column params
        for (int l = tid; l < BJ * HEADS; l += 256) {
            int j = l / HEADS, h = l % HEADS;
            colS[l] = ColP[(size_t)h * N + jBase + j];
        }
        __syncthreads();

        // build weight tile + accumulate denominators
#pragma unroll
        for (int jj = 0; jj < JS; jj++) {
            int j = slice * JS + jj;
            float4 cp = colS[j * HEADS + h_b];
            float t = rp.z + cp.x;                        // s1 + s2
            float w = (t >= 0.f) ? (rp.x * cp.y) : (rp.y * cp.z);
            w = adjS[r_b * (BJ + 1) + j] ? w : 0.f;
            Ws[j * PAIRS + h_b * BM + r_b] = w;
            denom_acc += w;
        }
        __syncthreads();

        // outer-product GEMM: acc[r][f] += w[r] * h[f]
#pragma unroll 4
        for (int j = 0; j < BJ; j++) {
            float hv[FPT];
#pragma unroll
            for (int v = 0; v < FPT / 4; v++)
                *(float4*)(hv + 4 * v) = *(const float4*)(Hs + j * F + f0 + 4 * v);
            float wv[RPT];
            if constexpr (RPT % 4 == 0) {
#pragma unroll
                for (int v = 0; v < RPT / 4; v++)
                    *(float4*)(wv + 4 * v) = *(const float4*)(Ws + j * PAIRS + headF * BM + r0 + 4 * v);
            } else {
#pragma unroll
                for (int r = 0; r < RPT; r++)
                    wv[r] = Ws[j * PAIRS + headF * BM + r0 + r];
            }
#pragma unroll
            for (int r = 0; r < RPT; r++)
#pragma unroll
                for (int f = 0; f < FPT; f++)
                    acc[r][f] = fmaf(wv[r], hv[f], acc[r][f]);
        }
        __syncthreads();
    }

#pragma unroll
    for (int r = 0; r < RPT; r++)
#pragma unroll
        for (int f = 0; f < FPT; f++)
            atomicAdd(&OutAcc[(size_t)(rowBase + r0 + r) * F + f0 + f], acc[r][f]);
    atomicAdd(&Den[(size_t)h_b * N + rowBase + r_b], denom_acc);
}

// ---------------- epilogues -------------------------------------------------
__device__ __forceinline__ float elu_f(float v) { return v > 0.f ? v : expm1f(v); }

__global__ void epilogue1_kernel(const float* __restrict__ OutAcc, const float* __restrict__ Den,
                                 float* __restrict__ X2) {
    int idx = blockIdx.x * 256 + threadIdx.x;
    if (idx >= N_NODES * F_HID) return;
    int i = idx / F_HID, f = idx % F_HID;
    float s = 0.f;
#pragma unroll
    for (int h = 0; h < NHEADS; h++) {
        float v = OutAcc[(size_t)i * (NHEADS * F_HID) + h * F_HID + f] / Den[(size_t)h * N_NODES + i];
        s += elu_f(v);
    }
    X2[idx] = s * 0.25f;
}

__global__ void epilogue2_kernel(const float* __restrict__ OutAcc, const float* __restrict__ Den,
                                 float* __restrict__ out) {
    int idx = blockIdx.x * 256 + threadIdx.x;
    if (idx >= N_NODES * F_OUT) return;
    int i = idx / F_OUT;
    float v = OutAcc[idx] / Den[i];
    out[idx] = elu_f(v);
}

// ---------------- launch ----------------------------------------------------
extern "C" void kernel_launch(void* const* d_in, const int* in_sizes, int n_in,
                              void* d_out, int out_size) {
    const float* x       = (const float*)d_in[0];
    const int*   adj     = (const int*)  d_in[1];
    const float* W_heads = (const float*)d_in[2];
    const float* a_heads = (const float*)d_in[3];
    const float* W_out   = (const float*)d_in[4];
    const float* a_out   = (const float*)d_in[5];
    float* out = (float*)d_out;
    const int N = N_NODES;

    float  *H1, *Wp, *s1, *s2, *s2m, *OutAcc1, *Den1, *X2, *H2, *OutAcc2, *Den2;
    float4 *RowP, *ColP;
    cudaGetSymbolAddress((void**)&H1,      g_H1);
    cudaGetSymbolAddress((void**)&Wp,      g_Wp);
    cudaGetSymbolAddress((void**)&s1,      g_s1);
    cudaGetSymbolAddress((void**)&s2,      g_s2);
    cudaGetSymbolAddress((void**)&s2m,     g_s2max);
    cudaGetSymbolAddress((void**)&RowP,    g_RowP);
    cudaGetSymbolAddress((void**)&ColP,    g_ColP);
    cudaGetSymbolAddress((void**)&OutAcc1, g_OutAcc1);
    cudaGetSymbolAddress((void**)&Den1,    g_Den1);
    cudaGetSymbolAddress((void**)&X2,      g_X2);
    cudaGetSymbolAddress((void**)&H2,      g_H2);
    cudaGetSymbolAddress((void**)&OutAcc2, g_OutAcc2);
    cudaGetSymbolAddress((void**)&Den2,    g_Den2);

    const int SMEM1 = (32 * 256 + 32 * 128) * 4 + 32 * 33 * 4 + 32 * 4 * 16;  // 55424
    const int SMEM2 = (32 * 32 + 32 * 32) * 4 + 32 * 33 * 4 + 32 * 1 * 16;    // 12928
    cudaFuncSetAttribute(heavy_kernel<32, 32, 4, 256, 4, 8>,
                         cudaFuncAttributeMaxDynamicSharedMemorySize, SMEM1);
    cudaFuncSetAttribute(heavy_kernel<32, 32, 1, 32, 1, 4>,
                         cudaFuncAttributeMaxDynamicSharedMemorySize, SMEM2);

    // zero accumulators (must happen every call: atomics accumulate)
    zero_kernel<<<(N * 256 + 255) / 256, 256>>>(OutAcc1, N * 256);
    zero_kernel<<<(4 * N + 255) / 256, 256>>>(Den1, 4 * N);
    zero_kernel<<<(N * 32 + 255) / 256, 256>>>(OutAcc2, N * 32);
    zero_kernel<<<(N + 255) / 256, 256>>>(Den2, N);

    // ---- layer 1 ----
    repack_kernel<<<256, 256>>>(W_heads, Wp);
    gemm_kernel<<<dim3(4, 96), 256>>>(x, Wp, H1, N, 256, 256);
    score_kernel<<<(N * 4 * 32 + 255) / 256, 256>>>(H1, a_heads, s1, s2, N, 64, 4);
    s2max_kernel<<<4, 256>>>(s2, s2m, N);
    param_kernel<<<(N * 4 + 255) / 256, 256>>>(s1, s2, s2m, RowP, ColP, N, 4);
    heavy_kernel<32, 32, 4, 256, 4, 8><<<dim3(192, 6), 256, SMEM1>>>(
        adj, H1, RowP, ColP, OutAcc1, Den1, N, N / 6);
    epilogue1_kernel<<<(N * 64 + 255) / 256, 256>>>(OutAcc1, Den1, X2);

    // ---- layer 2 ----
    gemm_kernel<<<dim3(1, 96), 256>>>(X2, W_out, H2, N, 32, 64);
    score_kernel<<<(N * 32 + 255) / 256, 256>>>(H2, a_out, s1, s2, N, 32, 1);
    s2max_kernel<<<1, 256>>>(s2, s2m, N);
    param_kernel<<<(N + 255) / 256, 256>>>(s1, s2, s2m, RowP, ColP, N, 1);
    heavy_kernel<32, 32, 1, 32, 1, 4><<<dim3(192, 6), 256, SMEM2>>>(
        adj, H2, RowP, ColP, OutAcc2, Den2, N, N / 6);
    epilogue2_kernel<<<(N * 32 + 255) / 256, 256>>>(OutAcc2, Den2, out);
}

// round 16
// speedup vs baseline: 1.6036x; 1.6036x over previous
#include <cuda_runtime.h>
#include <cuda_bf16.h>
#include <math.h>
#include <stdint.h>

#define N_NODES 6144
#define F_IN    256
#define F_HID   64
#define F_OUT   32
#define NHEADS  4
#define SPLITJ  6
#define HPAD    264
#define WLD     72

// ---------------- scratch --------------------------------------------------
__device__ float  g_H1[N_NODES * 256];
__device__ __align__(16) __nv_bfloat16 g_H1hi[N_NODES * HPAD];
__device__ __align__(16) __nv_bfloat16 g_H1lo[N_NODES * HPAD];
__device__ float  g_Wp[F_IN * 256];
__device__ float  g_s1[NHEADS * N_NODES];
__device__ float  g_s2[NHEADS * N_NODES];
__device__ float  g_s2max[NHEADS];
__device__ float4 g_RowP[NHEADS * N_NODES];
__device__ float4 g_ColP[NHEADS * N_NODES];
__device__ float  g_OutP[SPLITJ * N_NODES * 256];
__device__ float  g_DenP[SPLITJ * NHEADS * N_NODES];
__device__ float  g_X2[N_NODES * F_HID];
__device__ float  g_H2[N_NODES * F_OUT];
__device__ float  g_OutAcc2[N_NODES * F_OUT];
__device__ float  g_Den2[N_NODES];

// ---------------- small kernels --------------------------------------------
__global__ void zero_kernel(float* __restrict__ p, int n) {
    int i = blockIdx.x * 256 + threadIdx.x;
    if (i < n) p[i] = 0.f;
}

__global__ void repack_kernel(const float* __restrict__ W, float* __restrict__ Wp) {
    int idx = blockIdx.x * 256 + threadIdx.x;
    int k = idx >> 8, c = idx & 255, h = c >> 6, f = c & 63;
    Wp[idx] = W[h * (F_IN * F_HID) + k * F_HID + f];
}

__global__ void gemm_kernel(const float* __restrict__ A, const float* __restrict__ B,
                            float* __restrict__ C, int M, int Ncol, int K) {
    __shared__ float As[16][65];
    __shared__ float Bs[16][64];
    int tid = threadIdx.x;
    int tx = tid & 15, ty = tid >> 4;
    int rowBase = blockIdx.y * 64, colBase = blockIdx.x * 64;
    float acc[4][4] = {};
    for (int k0 = 0; k0 < K; k0 += 16) {
        for (int l = tid; l < 64 * 16; l += 256) {
            int r = l >> 4, kk = l & 15;
            As[kk][r] = A[(size_t)(rowBase + r) * K + k0 + kk];
        }
        for (int l = tid; l < 16 * 64; l += 256) {
            int kk = l >> 6, n = l & 63;
            int col = colBase + n;
            Bs[kk][n] = (col < Ncol) ? B[(size_t)(k0 + kk) * Ncol + col] : 0.f;
        }
        __syncthreads();
#pragma unroll
        for (int kk = 0; kk < 16; kk++) {
            float a[4], b[4];
#pragma unroll
            for (int i = 0; i < 4; i++) a[i] = As[kk][ty * 4 + i];
#pragma unroll
            for (int j = 0; j < 4; j++) b[j] = Bs[kk][tx * 4 + j];
#pragma unroll
            for (int i = 0; i < 4; i++)
#pragma unroll
                for (int j = 0; j < 4; j++) acc[i][j] = fmaf(a[i], b[j], acc[i][j]);
        }
        __syncthreads();
    }
#pragma unroll
    for (int i = 0; i < 4; i++) {
        int row = rowBase + ty * 4 + i;
#pragma unroll
        for (int j = 0; j < 4; j++) {
            int col = colBase + tx * 4 + j;
            if (col < Ncol) C[(size_t)row * Ncol + col] = acc[i][j];
        }
    }
}

__global__ void score_kernel(const float* __restrict__ H, const float* __restrict__ a,
                             float* __restrict__ s1o, float* __restrict__ s2o,
                             int N, int F, int heads) {
    int gt = blockIdx.x * blockDim.x + threadIdx.x;
    int w = gt >> 5, lane = gt & 31;
    if (w >= N * heads) return;
    int h = w / N, i = w - h * N;
    const float* hr = H + (size_t)i * F * heads + h * F;
    const float* a1 = a + h * 2 * F;
    const float* a2 = a1 + F;
    float p1 = 0.f, p2 = 0.f;
    for (int f = lane; f < F; f += 32) {
        float hv = hr[f];
        p1 = fmaf(hv, a1[f], p1);
        p2 = fmaf(hv, a2[f], p2);
    }
#pragma unroll
    for (int o = 16; o; o >>= 1) {
        p1 += __shfl_down_sync(0xffffffffu, p1, o);
        p2 += __shfl_down_sync(0xffffffffu, p2, o);
    }
    if (lane == 0) { s1o[w] = p1; s2o[w] = p2; }
}

__global__ void s2max_kernel(const float* __restrict__ s2, float* __restrict__ out, int N) {
    __shared__ float sm[256];
    const float* p = s2 + (size_t)blockIdx.x * N;
    float m = -1e30f;
    for (int i = threadIdx.x; i < N; i += 256) m = fmaxf(m, p[i]);
    sm[threadIdx.x] = m;
    __syncthreads();
    for (int s = 128; s; s >>= 1) {
        if (threadIdx.x < s) sm[threadIdx.x] = fmaxf(sm[threadIdx.x], sm[threadIdx.x + s]);
        __syncthreads();
    }
    if (threadIdx.x == 0) out[blockIdx.x] = sm[0];
}

__global__ void param_kernel(const float* __restrict__ s1, const float* __restrict__ s2,
                             const float* __restrict__ s2max,
                             float4* __restrict__ RowP, float4* __restrict__ ColP,
                             int N, int heads) {
    int idx = blockIdx.x * 256 + threadIdx.x;
    if (idx >= N * heads) return;
    int h = idx / N;
    float sv1 = s1[idx], sv2 = s2[idx];
    float t = sv1 + s2max[h];
    float m = (t > 0.f) ? t : 0.2f * t;
    RowP[idx] = make_float4(expf(sv1 - m), expf(0.2f * sv1 - m), sv1, 0.f);
    ColP[idx] = make_float4(sv2, expf(sv2), expf(0.2f * sv2), 0.f);
}

// split H1 fp32 [N][256] -> padded bf16 hi/lo [N][HPAD]
__global__ void hsplit_kernel(const float* __restrict__ H,
                              __nv_bfloat16* __restrict__ Hhi,
                              __nv_bfloat16* __restrict__ Hlo) {
    int idx = blockIdx.x * 256 + threadIdx.x;
    int i = idx >> 8, f = idx & 255;
    float v = H[idx];
    __nv_bfloat16 hi = __float2bfloat16(v);
    float rem = v - __bfloat162float(hi);
    Hhi[(size_t)i * HPAD + f] = hi;
    Hlo[(size_t)i * HPAD + f] = __float2bfloat16(rem);
}

// ---------------- MMA helpers -----------------------------------------------
__device__ __forceinline__ void ldsm4(uint32_t* r, uint32_t a) {
    asm volatile("ldmatrix.sync.aligned.m8n8.x4.shared.b16 {%0,%1,%2,%3}, [%4];"
                 : "=r"(r[0]), "=r"(r[1]), "=r"(r[2]), "=r"(r[3]) : "r"(a));
}
__device__ __forceinline__ void ldsm4t(uint32_t* r, uint32_t a) {
    asm volatile("ldmatrix.sync.aligned.m8n8.x4.trans.shared.b16 {%0,%1,%2,%3}, [%4];"
                 : "=r"(r[0]), "=r"(r[1]), "=r"(r[2]), "=r"(r[3]) : "r"(a));
}
__device__ __forceinline__ void mma_bf16(float* c, const uint32_t* a, const uint32_t* b) {
    asm volatile("mma.sync.aligned.m16n8k16.row.col.f32.bf16.bf16.f32 "
                 "{%0,%1,%2,%3},{%4,%5,%6,%7},{%8,%9},{%0,%1,%2,%3};"
                 : "+f"(c[0]), "+f"(c[1]), "+f"(c[2]), "+f"(c[3])
                 : "r"(a[0]), "r"(a[1]), "r"(a[2]), "r"(a[3]), "r"(b[0]), "r"(b[1]));
}

// ---------------- heavy layer-1 (tensor core) -------------------------------
// smem: [0) HsHi 64xHPAD bf16 (33792B) | HsLo (33792B) | W 8x(64xWLD bf16) (73728B)
//       | colS float4[256] (4096B).  Total dynamic = 145408 B.
#define HS_BYTES 33792
#define W_OFF    67584
#define W_TILE   9216
#define COLS_OFF 141312
#define SMEM1_TOT 145408

__global__ void __launch_bounds__(256)
heavy1_mma(const int* __restrict__ adj,
           const __nv_bfloat16* __restrict__ Ghi, const __nv_bfloat16* __restrict__ Glo,
           const float4* __restrict__ RowP, const float4* __restrict__ ColP,
           float* __restrict__ OutP, float* __restrict__ DenP, int jPerBlock) {
    extern __shared__ char smc[];
    __shared__ float denS[4][256];
    const uint32_t smBase = (uint32_t)__cvta_generic_to_shared(smc);
    const uint32_t hsHi = smBase;
    const uint32_t wBase = smBase + W_OFF;
    float4* colS = (float4*)(smc + COLS_OFF);

    const int tid = threadIdx.x;
    const int lane = tid & 31;
    const int warp = tid >> 5;
    const int rowBase = blockIdx.x * 64;
    const int jBase0 = blockIdx.y * jPerBlock;

    // build-phase mapping: bi = row, bjb = 16-j block
    const int bi = tid & 63;
    const int bjb = tid >> 6;
    float rA[4], rB[4], rS[4], den[4];
#pragma unroll
    for (int h = 0; h < 4; h++) {
        float4 rp = RowP[(size_t)h * N_NODES + rowBase + bi];
        rA[h] = rp.x; rB[h] = rp.y; rS[h] = rp.z; den[h] = 0.f;
    }

    // mma-phase mapping
    const int head = warp >> 1;
    const int f0 = head * 64 + (warp & 1) * 32;
    const int ldRow = (lane & 7) + ((lane >> 3) & 1) * 8;
    const int ldCol = (lane >> 4) * 8;
    float acc[4][4][4];
#pragma unroll
    for (int a = 0; a < 4; a++)
#pragma unroll
        for (int b = 0; b < 4; b++)
#pragma unroll
            for (int c = 0; c < 4; c++) acc[a][b][c] = 0.f;

    const int chunks = jPerBlock >> 6;
    for (int c = 0; c < chunks; c++) {
        const int jBase = jBase0 + (c << 6);

        // stage column params + H chunk (pitch-matched flat copy)
        {
            int j = tid >> 2, h = tid & 3;
            colS[tid] = ColP[(size_t)h * N_NODES + jBase + j];
        }
        {
            const float4* ghi = (const float4*)(Ghi + (size_t)jBase * HPAD);
            const float4* glo = (const float4*)(Glo + (size_t)jBase * HPAD);
            float4* shi = (float4*)smc;
            float4* slo = (float4*)(smc + HS_BYTES);
            for (int l = tid; l < 64 * HPAD / 8; l += 256) {
                shi[l] = ghi[l];
                slo[l] = glo[l];
            }
        }
        __syncthreads();

        // build W tiles (hi/lo bf16) + denominators
        {
            const int4* arow = (const int4*)(adj + (size_t)(rowBase + bi) * N_NODES + jBase + bjb * 16);
            int am[16];
            *(int4*)&am[0]  = arow[0];
            *(int4*)&am[4]  = arow[1];
            *(int4*)&am[8]  = arow[2];
            *(int4*)&am[12] = arow[3];
#pragma unroll
            for (int h = 0; h < 4; h++) {
                uint32_t uhi[8], ulo[8];
#pragma unroll
                for (int q = 0; q < 8; q++) {
                    float4 c0 = colS[((bjb * 16 + 2 * q) << 2) + h];
                    float4 c1 = colS[((bjb * 16 + 2 * q + 1) << 2) + h];
                    float t0 = rS[h] + c0.x;
                    float w0 = (t0 >= 0.f) ? rA[h] * c0.y : rB[h] * c0.z;
                    w0 = am[2 * q] ? w0 : 0.f;
                    float t1 = rS[h] + c1.x;
                    float w1 = (t1 >= 0.f) ? rA[h] * c1.y : rB[h] * c1.z;
                    w1 = am[2 * q + 1] ? w1 : 0.f;
                    den[h] += w0 + w1;
                    __nv_bfloat16 h0 = __float2bfloat16(w0), h1 = __float2bfloat16(w1);
                    __nv_bfloat16 l0 = __float2bfloat16(w0 - __bfloat162float(h0));
                    __nv_bfloat16 l1 = __float2bfloat16(w1 - __bfloat162float(h1));
                    uhi[q] = (uint32_t)__bfloat16_as_ushort(h0) |
                             ((uint32_t)__bfloat16_as_ushort(h1) << 16);
                    ulo[q] = (uint32_t)__bfloat16_as_ushort(l0) |
                             ((uint32_t)__bfloat16_as_ushort(l1) << 16);
                }
                char* wp = smc + W_OFF + (h * 2) * W_TILE + bi * (WLD * 2) + bjb * 32;
                *(uint4*)wp                   = make_uint4(uhi[0], uhi[1], uhi[2], uhi[3]);
                *(uint4*)(wp + 16)            = make_uint4(uhi[4], uhi[5], uhi[6], uhi[7]);
                *(uint4*)(wp + W_TILE)        = make_uint4(ulo[0], ulo[1], ulo[2], ulo[3]);
                *(uint4*)(wp + W_TILE + 16)   = make_uint4(ulo[4], ulo[5], ulo[6], ulo[7]);
            }
        }
        __syncthreads();

        // tensor-core phase: acc += Whi*Hhi + Whi*Hlo + Wlo*Hhi
#pragma unroll
        for (int ks = 0; ks < 4; ks++) {
            const int k0 = ks * 16;
            uint32_t ah[4][4], al[4][4];
#pragma unroll
            for (int mt = 0; mt < 4; mt++) {
                uint32_t base = wBase + (head * 2) * W_TILE +
                                (uint32_t)(((mt * 16 + ldRow) * WLD + k0 + ldCol) * 2);
                ldsm4(ah[mt], base);
                ldsm4(al[mt], base + W_TILE);
            }
            uint32_t bh[4][2], bl[4][2];
#pragma unroll
            for (int g = 0; g < 2; g++) {
                uint32_t addr = hsHi + (uint32_t)(((k0 + ldRow) * HPAD + f0 + g * 16 + ldCol) * 2);
                uint32_t r[4];
                ldsm4t(r, addr);
                bh[g * 2][0] = r[0]; bh[g * 2][1] = r[1];
                bh[g * 2 + 1][0] = r[2]; bh[g * 2 + 1][1] = r[3];
                ldsm4t(r, addr + HS_BYTES);
                bl[g * 2][0] = r[0]; bl[g * 2][1] = r[1];
                bl[g * 2 + 1][0] = r[2]; bl[g * 2 + 1][1] = r[3];
            }
#pragma unroll
            for (int mt = 0; mt < 4; mt++)
#pragma unroll
                for (int nt = 0; nt < 4; nt++) {
                    mma_bf16(acc[mt][nt], ah[mt], bh[nt]);
                    mma_bf16(acc[mt][nt], ah[mt], bl[nt]);
                    mma_bf16(acc[mt][nt], al[mt], bh[nt]);
                }
        }
        __syncthreads();
    }

    // write partial outputs (no atomics; per-y-slice buffer)
    float* outp = OutP + (size_t)blockIdx.y * (N_NODES * 256);
    const int gr = lane >> 2, tc2 = (lane & 3) * 2;
#pragma unroll
    for (int mt = 0; mt < 4; mt++) {
        int r0g = rowBase + mt * 16 + gr;
#pragma unroll
        for (int nt = 0; nt < 4; nt++) {
            int col = f0 + nt * 8 + tc2;
            *(float2*)&outp[(size_t)r0g * 256 + col] = make_float2(acc[mt][nt][0], acc[mt][nt][1]);
            *(float2*)&outp[(size_t)(r0g + 8) * 256 + col] = make_float2(acc[mt][nt][2], acc[mt][nt][3]);
        }
    }
    // reduce denominators over the 4 j-blocks
#pragma unroll
    for (int h = 0; h < 4; h++) denS[h][tid] = den[h];
    __syncthreads();
    {
        int h = tid >> 6, i2 = tid & 63;
        float d = denS[h][i2] + denS[h][64 + i2] + denS[h][128 + i2] + denS[h][192 + i2];
        DenP[(size_t)blockIdx.y * (4 * N_NODES) + (size_t)h * N_NODES + rowBase + i2] = d;
    }
}

// ---------------- heavy layer-2 (fp32, proven path) -------------------------
template <int BM, int BJ, int HEADS, int F, int RPT, int FPT>
__global__ void __launch_bounds__(256, 2)
heavy_kernel(const int* __restrict__ adj, const float* __restrict__ H,
             const float4* __restrict__ RowP, const float4* __restrict__ ColP,
             float* __restrict__ OutAcc, float* __restrict__ Den,
             int N, int jPerBlock) {
    constexpr int FPH    = F / HEADS;
    constexpr int FG     = F / FPT;
    constexpr int PAIRS  = HEADS * BM;
    constexpr int NSLICE = 256 / PAIRS;
    constexpr int JS     = BJ / NSLICE;

    extern __shared__ float smem[];
    float*  Hs   = smem;
    float*  Ws   = Hs + BJ * F;
    int*    adjS = (int*)(Ws + BJ * PAIRS);
    float4* colS = (float4*)(adjS + BM * (BJ + 1));

    int tid = threadIdx.x;
    int rowBase = blockIdx.x * BM;
    int jBase0  = blockIdx.y * jPerBlock;

    int rg = tid / FG, fg = tid % FG;
    int r0 = rg * RPT, f0 = fg * FPT;
    int headF = f0 / FPH;

    int p = tid % PAIRS;
    int slice = tid / PAIRS;
    int h_b = p / BM, r_b = p % BM;
    float4 rp = RowP[(size_t)h_b * N + rowBase + r_b];
    float denom_acc = 0.f;

    float acc[RPT][FPT];
#pragma unroll
    for (int r = 0; r < RPT; r++)
#pragma unroll
        for (int f = 0; f < FPT; f++) acc[r][f] = 0.f;

    for (int jc = 0; jc < jPerBlock; jc += BJ) {
        int jBase = jBase0 + jc;
        for (int l = tid; l < BM * BJ; l += 256) {
            int r = l / BJ, j = l % BJ;
            adjS[r * (BJ + 1) + j] = adj[(size_t)(rowBase + r) * N + jBase + j];
        }
        for (int l = tid; l < BJ * F / 4; l += 256)
            ((float4*)Hs)[l] = ((const float4*)H)[(size_t)jBase * (F / 4) + l];
        for (int l = tid; l < BJ * HEADS; l += 256) {
            int j = l / HEADS, h = l % HEADS;
            colS[l] = ColP[(size_t)h * N + jBase + j];
        }
        __syncthreads();

#pragma unroll
        for (int jj = 0; jj < JS; jj++) {
            int j = slice * JS + jj;
            float4 cp = colS[j * HEADS + h_b];
            float t = rp.z + cp.x;
            float w = (t >= 0.f) ? (rp.x * cp.y) : (rp.y * cp.z);
            w = adjS[r_b * (BJ + 1) + j] ? w : 0.f;
            Ws[j * PAIRS + h_b * BM + r_b] = w;
            denom_acc += w;
        }
        __syncthreads();

#pragma unroll 4
        for (int j = 0; j < BJ; j++) {
            float hv[FPT];
#pragma unroll
            for (int v = 0; v < FPT / 4; v++)
                *(float4*)(hv + 4 * v) = *(const float4*)(Hs + j * F + f0 + 4 * v);
            float wv[RPT];
#pragma unroll
            for (int r = 0; r < RPT; r++)
                wv[r] = Ws[j * PAIRS + headF * BM + r0 + r];
#pragma unroll
            for (int r = 0; r < RPT; r++)
#pragma unroll
                for (int f = 0; f < FPT; f++)
                    acc[r][f] = fmaf(wv[r], hv[f], acc[r][f]);
        }
        __syncthreads();
    }

#pragma unroll
    for (int r = 0; r < RPT; r++)
#pragma unroll
        for (int f = 0; f < FPT; f++)
            atomicAdd(&OutAcc[(size_t)(rowBase + r0 + r) * F + f0 + f], acc[r][f]);
    atomicAdd(&Den[(size_t)h_b * N + rowBase + r_b], denom_acc);
}

// ---------------- epilogues -------------------------------------------------
__device__ __forceinline__ float elu_f(float v) { return v > 0.f ? v : expm1f(v); }

__global__ void epilogue1_kernel(const float* __restrict__ OutP, const float* __restrict__ DenP,
                                 float* __restrict__ X2) {
    int idx = blockIdx.x * 256 + threadIdx.x;
    if (idx >= N_NODES * F_HID) return;
    int i = idx >> 6, f = idx & 63;
    float s = 0.f;
#pragma unroll
    for (int h = 0; h < NHEADS; h++) {
        float num = 0.f, den = 0.f;
#pragma unroll
        for (int p = 0; p < SPLITJ; p++) {
            num += OutP[(size_t)p * (N_NODES * 256) + (size_t)i * 256 + h * 64 + f];
            den += DenP[(size_t)p * (4 * N_NODES) + (size_t)h * N_NODES + i];
        }
        s += elu_f(num / den);
    }
    X2[idx] = s * 0.25f;
}

__global__ void epilogue2_kernel(const float* __restrict__ OutAcc, const float* __restrict__ Den,
                                 float* __restrict__ out) {
    int idx = blockIdx.x * 256 + threadIdx.x;
    if (idx >= N_NODES * F_OUT) return;
    int i = idx / F_OUT;
    out[idx] = elu_f(OutAcc[idx] / Den[i]);
}

// ---------------- launch ----------------------------------------------------
extern "C" void kernel_launch(void* const* d_in, const int* in_sizes, int n_in,
                              void* d_out, int out_size) {
    const float* x       = (const float*)d_in[0];
    const int*   adj     = (const int*)  d_in[1];
    const float* W_heads = (const float*)d_in[2];
    const float* a_heads = (const float*)d_in[3];
    const float* W_out   = (const float*)d_in[4];
    const float* a_out   = (const float*)d_in[5];
    float* out = (float*)d_out;
    const int N = N_NODES;

    float *H1, *Wp, *s1, *s2, *s2m, *OutP, *DenP, *X2, *H2, *OutAcc2, *Den2;
    float4 *RowP, *ColP;
    __nv_bfloat16 *H1hi, *H1lo;
    cudaGetSymbolAddress((void**)&H1,      g_H1);
    cudaGetSymbolAddress((void**)&H1hi,    g_H1hi);
    cudaGetSymbolAddress((void**)&H1lo,    g_H1lo);
    cudaGetSymbolAddress((void**)&Wp,      g_Wp);
    cudaGetSymbolAddress((void**)&s1,      g_s1);
    cudaGetSymbolAddress((void**)&s2,      g_s2);
    cudaGetSymbolAddress((void**)&s2m,     g_s2max);
    cudaGetSymbolAddress((void**)&RowP,    g_RowP);
    cudaGetSymbolAddress((void**)&ColP,    g_ColP);
    cudaGetSymbolAddress((void**)&OutP,    g_OutP);
    cudaGetSymbolAddress((void**)&DenP,    g_DenP);
    cudaGetSymbolAddress((void**)&X2,      g_X2);
    cudaGetSymbolAddress((void**)&H2,      g_H2);
    cudaGetSymbolAddress((void**)&OutAcc2, g_OutAcc2);
    cudaGetSymbolAddress((void**)&Den2,    g_Den2);

    const int SMEM2 = (32 * 32 + 32 * 32) * 4 + 32 * 33 * 4 + 32 * 1 * 16;
    cudaFuncSetAttribute(heavy1_mma, cudaFuncAttributeMaxDynamicSharedMemorySize, SMEM1_TOT);
    cudaFuncSetAttribute(heavy_kernel<32, 32, 1, 32, 1, 4>,
                         cudaFuncAttributeMaxDynamicSharedMemorySize, SMEM2);

    // zero only layer-2 accumulators (layer 1 uses partial buffers, no atomics)
    zero_kernel<<<(N * 32 + 255) / 256, 256>>>(OutAcc2, N * 32);
    zero_kernel<<<(N + 255) / 256, 256>>>(Den2, N);

    // ---- layer 1 ----
    repack_kernel<<<256, 256>>>(W_heads, Wp);
    gemm_kernel<<<dim3(4, 96), 256>>>(x, Wp, H1, N, 256, 256);
    score_kernel<<<(N * 4 * 32 + 255) / 256, 256>>>(H1, a_heads, s1, s2, N, 64, 4);
    s2max_kernel<<<4, 256>>>(s2, s2m, N);
    param_kernel<<<(N * 4 + 255) / 256, 256>>>(s1, s2, s2m, RowP, ColP, N, 4);
    hsplit_kernel<<<(N * 256) / 256, 256>>>(H1, H1hi, H1lo);
    heavy1_mma<<<dim3(96, SPLITJ), 256, SMEM1_TOT>>>(adj, H1hi, H1lo, RowP, ColP,
                                                     OutP, DenP, N / SPLITJ);
    epilogue1_kernel<<<(N * 64 + 255) / 256, 256>>>(OutP, DenP, X2);

    // ---- layer 2 ----
    gemm_kernel<<<dim3(1, 96), 256>>>(X2, W_out, H2, N, 32, 64);
    score_kernel<<<(N * 32 + 255) / 256, 256>>>(H2, a_out, s1, s2, N, 32, 1);
    s2max_kernel<<<1, 256>>>(s2, s2m, N);
    param_kernel<<<(N + 255) / 256, 256>>>(s1, s2, s2m, RowP, ColP, N, 1);
    heavy_kernel<32, 32, 1, 32, 1, 4><<<dim3(192, 6), 256, SMEM2>>>(
        adj, H2, RowP, ColP, OutAcc2, Den2, N, N / 6);
    epilogue2_kernel<<<(N * 32 + 255) / 256, 256>>>(OutAcc2, Den2, out);
}